// round 16
// baseline (speedup 1.0000x reference)
#include <cuda_runtime.h>
#include <math.h>

#define NPTS   2048
#define NT     128
#define NW     (NT/32)      // 4 warps
#define MAXPTS 100
#define F_INF  (__int_as_float(0x7f800000))

typedef unsigned long long u64;
typedef unsigned int       u32;

static __device__ __forceinline__ u64 umax64(u64 a, u64 b) { return a > b ? a : b; }

template<int E> struct Regs { float x2[E], y2[E], z2[E], sq[E], mk[E]; };

// per-thread argmin: fold tail onto largest pow2 <= E, then halve (compare-select)
template<int E>
static __device__ __forceinline__ void argmin_tree(const float (&v)[E],
                                                   float& outv, int& outi)
{
    float bv[E]; int bi[E];
    #pragma unroll
    for (int e = 0; e < E; e++) { bv[e] = v[e]; bi[e] = e; }
    constexpr int T = ((E & (E - 1)) == 0) ? E : (E > 8 ? 8 : (E > 4 ? 4 : 2));
    #pragma unroll
    for (int e = T; e < E; e++) {
        bool c = bv[e] < bv[e - T];
        bv[e - T] = c ? bv[e] : bv[e - T];
        bi[e - T] = c ? bi[e] : bi[e - T];
    }
    #pragma unroll
    for (int st = T / 2; st >= 1; st >>= 1) {
        #pragma unroll
        for (int e = 0; e < st; e++) {
            bool c = bv[e + st] < bv[e];
            bv[e] = c ? bv[e + st] : bv[e];
            bi[e] = c ? bi[e + st] : bi[e];
        }
    }
    outv = bv[0]; outi = bi[0];
}

// ---------- multi-warp Prim phase ----------
// tbl = raw (x,y,z,|x|^2); regs hold -2x. Broadcast coords q carried across steps;
// post-barrier: 4 speculative broadcast loads overlap the u32 value-compare tree.
template<int E>
static __device__ __forceinline__ void prim_run(
    const float4* __restrict__ tbl, float* __restrict__ sdeath,
    u64 (&wred)[2][NW], Regs<E>& R,
    int gbase, int tid, int wid,
    int& j, int& p, int step0, int nsteps)
{
    const float inf = F_INF;
    float4 q = tbl[j];                            // phase-entry broadcast
    #pragma unroll 1
    for (int s = 0; s < nsteps; s++) {
        #pragma unroll
        for (int e = 0; e < E; e++) {
            int gi = gbase + e;
            bool rem = (gi == j);
            float rs = rem ? inf : R.sq[e];       // permanent poison of removed vertex
            R.sq[e] = rs;
            float acc = fmaf(q.x, R.x2[e], rs + q.w);
            acc = fmaf(q.y, R.y2[e], acc);
            acc = fmaf(q.z, R.z2[e], acc);
            float mi = rem ? inf : R.mk[e];
            R.mk[e] = fminf(mi, fabsf(acc));      // >=0 -> u32 bit-order exact
        }
        float tm; int te;
        argmin_tree<E>(R.mk, tm, te);
        u32 ti = (u32)(gbase + te);

        u32 vb = __float_as_uint(tm);
        u32 r1 = __reduce_min_sync(0xffffffffu, vb);
        if (vb == r1) wred[p][wid] = ((u64)r1 << 32) | (u64)ti;  // STS.64: pair consistent

        __syncthreads();

        ulonglong2 wa = *reinterpret_cast<const ulonglong2*>(&wred[p][0]);
        ulonglong2 wb = *reinterpret_cast<const ulonglong2*>(&wred[p][2]);
        u32 v0 = (u32)(wa.x >> 32), i0 = (u32)wa.x;
        u32 v1 = (u32)(wa.y >> 32), i1 = (u32)wa.y;
        u32 v2 = (u32)(wb.x >> 32), i2 = (u32)wb.x;
        u32 v3 = (u32)(wb.y >> 32), i3 = (u32)wb.y;
        // speculative broadcast loads of all 4 candidates (overlap the tree)
        float4 q0 = tbl[i0], q1 = tbl[i1], q2 = tbl[i2], q3 = tbl[i3];
        bool c01 = v1 < v0;
        u32 va = c01 ? v1 : v0;  u32 ia = c01 ? i1 : i0;
        bool c23 = v3 < v2;
        u32 vc = c23 ? v3 : v2;  u32 ic = c23 ? i3 : i2;
        bool cf = vc < va;
        u32 vf = cf ? vc : va;
        j = (int)(cf ? ic : ia);
        float4 qa, qc;
        qa.x = c01 ? q1.x : q0.x; qa.y = c01 ? q1.y : q0.y;
        qa.z = c01 ? q1.z : q0.z; qa.w = c01 ? q1.w : q0.w;
        qc.x = c23 ? q3.x : q2.x; qc.y = c23 ? q3.y : q2.y;
        qc.z = c23 ? q3.z : q2.z; qc.w = c23 ? q3.w : q2.w;
        q.x = cf ? qc.x : qa.x; q.y = cf ? qc.y : qa.y;
        q.z = cf ? qc.z : qa.z; q.w = cf ? qc.w : qa.w;

        if (tid == 0) sdeath[step0 + s] = __uint_as_float(vf);
        p ^= 1;
    }
}

// ---------- single-warp Prim phase (warp 0, no block barriers) ----------
template<int E>
static __device__ __forceinline__ void prim_warp(
    const float4* __restrict__ tbl, float* __restrict__ sdeath,
    Regs<E>& R, int gbase, int lane, int& j, int step0, int nsteps)
{
    const float inf = F_INF;
    #pragma unroll 1
    for (int s = 0; s < nsteps; s++) {
        float4 q = tbl[j];
        #pragma unroll
        for (int e = 0; e < E; e++) {
            int gi = gbase + e;
            bool rem = (gi == j);
            float rs = rem ? inf : R.sq[e];
            R.sq[e] = rs;
            float acc = fmaf(q.x, R.x2[e], rs + q.w);
            acc = fmaf(q.y, R.y2[e], acc);
            acc = fmaf(q.z, R.z2[e], acc);
            float mi = rem ? inf : R.mk[e];
            R.mk[e] = fminf(mi, fabsf(acc));
        }
        float tm; int te;
        argmin_tree<E>(R.mk, tm, te);
        u32 ti = (u32)(gbase + te);

        u32 vb = __float_as_uint(tm);
        u32 r1 = __reduce_min_sync(0xffffffffu, vb);
        u32 msk = __ballot_sync(0xffffffffu, vb == r1);
        int src = __ffs(msk) - 1;
        j = __shfl_sync(0xffffffffu, (int)ti, src);
        if (lane == 0) sdeath[step0 + s] = __uint_as_float(r1);
    }
}

// ---------- block-wide compaction: alive -> tbl[0..newcap-2], winner at newcap-1 ----------
template<int E>
static __device__ __forceinline__ void compact_block(
    float4* tbl, float* smk, int* scnt,
    Regs<E>& R, int gbase, int tid, int j, int newcap)
{
    const float inf = F_INF;
    #pragma unroll
    for (int e = 0; e < E; e++)
        if (gbase + e == j) { R.sq[e] = inf; R.mk[e] = inf; }   // pending poison
    float4 win = tbl[j];                    // read winner BEFORE overwrite
    __syncthreads();
    if (tid == 0) { tbl[newcap - 1] = win; smk[newcap - 1] = inf; }
    int na = 0;
    #pragma unroll
    for (int e = 0; e < E; e++) na += (R.mk[e] != inf);
    int base = atomicAdd(scnt, na);
    #pragma unroll
    for (int e = 0; e < E; e++) {
        if (R.mk[e] != inf) {
            tbl[base] = make_float4(-0.5f * R.x2[e], -0.5f * R.y2[e],
                                    -0.5f * R.z2[e], R.sq[e]);
            smk[base] = R.mk[e];
            base++;
        }
    }
    __syncthreads();
}

// ---------- warp-0-only compaction ----------
template<int E>
static __device__ __forceinline__ void compact_warp(
    float4* tbl, float* smk, int* scnt,
    Regs<E>& R, int gbase, int lane, int j, int newcap)
{
    const float inf = F_INF;
    #pragma unroll
    for (int e = 0; e < E; e++)
        if (gbase + e == j) { R.sq[e] = inf; R.mk[e] = inf; }
    float4 win = tbl[j];
    __syncwarp();
    if (lane == 0) { tbl[newcap - 1] = win; smk[newcap - 1] = inf; }
    int na = 0;
    #pragma unroll
    for (int e = 0; e < E; e++) na += (R.mk[e] != inf);
    int base = atomicAdd(scnt, na);
    #pragma unroll
    for (int e = 0; e < E; e++) {
        if (R.mk[e] != inf) {
            tbl[base] = make_float4(-0.5f * R.x2[e], -0.5f * R.y2[e],
                                    -0.5f * R.z2[e], R.sq[e]);
            smk[base] = R.mk[e];
            base++;
        }
    }
    __syncwarp();
}

template<int E>
static __device__ __forceinline__ void reload(
    const float4* tbl, const float* smk, Regs<E>& R, int gbase, int cap)
{
    #pragma unroll
    for (int e = 0; e < E; e++) {
        int i = gbase + e;
        float4 t = tbl[i];
        R.x2[e] = -2.0f * t.x; R.y2[e] = -2.0f * t.y; R.z2[e] = -2.0f * t.z;
        R.sq[e] = (i == cap - 1) ? F_INF : t.w;     // winner pad inert
        R.mk[e] = smk[i];
    }
}

__global__ __launch_bounds__(NT, 1)
void ph_kernel(const float* __restrict__ x,
               const float* __restrict__ filt,
               float* __restrict__ out,
               int B, int F)
{
    __shared__ __align__(16) float4 tbl[NPTS];     // raw (x,y,z,|x|^2), reused
    __shared__ __align__(16) float  sdeath[NPTS];
    __shared__ float  smk[1792];
    __shared__ __align__(16) u64 wred[2][NW];
    __shared__ int    scnt[8];

    const int b     = blockIdx.x;
    const int tid   = threadIdx.x;
    const int lane  = tid & 31;
    const int wid   = tid >> 5;
    const float inf = F_INF;

    const float* xb = x + (long)b * NPTS * 3;

    // ---- load: premultiplied regs (E=16), raw table ----
    Regs<16> R1;
    {
        int gbase = tid << 4;
        #pragma unroll
        for (int e = 0; e < 16; e++) {
            int i = gbase + e;
            float a = xb[3*i + 0];
            float c = xb[3*i + 1];
            float d = xb[3*i + 2];
            float s = fmaf(a, a, fmaf(c, c, d * d));
            R1.x2[e] = -2.0f * a; R1.y2[e] = -2.0f * c; R1.z2[e] = -2.0f * d;
            R1.sq[e] = s; R1.mk[e] = inf;
            tbl[i] = make_float4(a, c, d, s);
        }
    }
    if (tid < 8) scnt[tid] = 0;
    __syncthreads();

    int j = 0, p = 0;

    // ---- dense staircase: compact every 256 steps (multi-warp region) ----
    // cap 2048, E16, steps 0..255
    prim_run<16>(tbl, sdeath, wred, R1, tid << 4, tid, wid, j, p, 0, 256);

    // -> 1792, E14, steps 256..511
    compact_block<16>(tbl, smk, &scnt[0], R1, tid << 4, tid, j, 1792);
    Regs<14> R2;
    reload<14>(tbl, smk, R2, tid * 14, 1792);
    j = 1791;
    prim_run<14>(tbl, sdeath, wred, R2, tid * 14, tid, wid, j, p, 256, 256);

    // -> 1536, E12, steps 512..767
    compact_block<14>(tbl, smk, &scnt[1], R2, tid * 14, tid, j, 1536);
    Regs<12> R3;
    reload<12>(tbl, smk, R3, tid * 12, 1536);
    j = 1535;
    prim_run<12>(tbl, sdeath, wred, R3, tid * 12, tid, wid, j, p, 512, 256);

    // -> 1280, E10, steps 768..1023
    compact_block<12>(tbl, smk, &scnt[2], R3, tid * 12, tid, j, 1280);
    Regs<10> R4;
    reload<10>(tbl, smk, R4, tid * 10, 1280);
    j = 1279;
    prim_run<10>(tbl, sdeath, wred, R4, tid * 10, tid, wid, j, p, 768, 256);

    // -> 1024, E8, steps 1024..1279
    compact_block<10>(tbl, smk, &scnt[3], R4, tid * 10, tid, j, 1024);
    Regs<8> R5;
    reload<8>(tbl, smk, R5, tid << 3, 1024);
    j = 1023;
    prim_run<8>(tbl, sdeath, wred, R5, tid << 3, tid, wid, j, p, 1024, 256);

    // -> 768, E6, steps 1280..1535
    compact_block<8>(tbl, smk, &scnt[4], R5, tid << 3, tid, j, 768);
    Regs<6> R6;
    reload<6>(tbl, smk, R6, tid * 6, 768);
    j = 767;
    prim_run<6>(tbl, sdeath, wred, R6, tid * 6, tid, wid, j, p, 1280, 256);

    // -> 512, E4, steps 1536..1791
    compact_block<6>(tbl, smk, &scnt[5], R6, tid * 6, tid, j, 512);
    Regs<4> R7;
    reload<4>(tbl, smk, R7, tid << 2, 512);
    j = 511;
    prim_run<4>(tbl, sdeath, wred, R7, tid << 2, tid, wid, j, p, 1536, 256);

    // -> 256: single warp, E8/lane, steps 1792..2046
    compact_block<4>(tbl, smk, &scnt[6], R7, tid << 2, tid, j, 256);
    if (wid == 0) {
        Regs<8> Q;
        reload<8>(tbl, smk, Q, lane << 3, 256);
        int jw = 255;
        prim_warp<8>(tbl, sdeath, Q, lane << 3, lane, jw, 1792, 255);
    }
    __syncthreads();

    // ---- d^2 -> death = sqrt(d2); pad slot 2047 with +INF ----
    #pragma unroll
    for (int e = 0; e < 16; e++) {
        int i = (tid << 4) + e;
        float d2 = sdeath[i];
        sdeath[i] = (i < NPTS - 1) ? sqrtf(d2) : inf;
    }
    __syncthreads();

    const long dgm_base = (long)b * 3 * MAXPTS * 2;                     // diagrams [B,3,100,2]
    const long bet_base = (long)B * 3 * MAXPTS * 2 + (long)b * 3 * F;   // betti    [B,3,F]

    // ---- zero-fill H1/H2 diagram slices and betti rows 1,2 ----
    for (int i = tid; i < 2 * MAXPTS * 2; i += NT)
        out[dgm_base + MAXPTS * 2 + i] = 0.0f;
    for (int i = tid; i < 2 * F; i += NT)
        out[bet_base + F + i] = 0.0f;

    // ---- Betti-0: one threshold per thread, float4 smem scan ----
    if (tid < F) {
        float ff = filt[tid];
        int cnt = 0;
        for (int i = 0; i < NPTS; i += 4) {
            float4 v = *reinterpret_cast<const float4*>(&sdeath[i]);
            cnt += (v.x <= ff) + (v.y <= ff) + (v.z <= ff) + (v.w <= ff);
        }
        out[bet_base + tid] = (float)(NPTS - cnt);
    }
    __syncthreads();

    // ---- top-100 deaths desc: iterative max extraction (R14 form) ----
    int jp = -1;
    p = 0;
    const int gbase = tid << 4;
    #pragma unroll 1
    for (int k = 0; k < MAXPTS; k++) {
        float bv[16]; int bi[16];
        #pragma unroll
        for (int e = 0; e < 16; e++) {
            int gi = gbase + e;
            float v = sdeath[gi];
            bv[e] = (gi == jp || gi == NPTS - 1) ? 0.0f : v;  // mask pending + INF pad
            bi[e] = e;
        }
        #pragma unroll
        for (int st = 8; st >= 1; st >>= 1) {
            #pragma unroll
            for (int e = 0; e < st; e++) {
                bool c = bv[e+st] > bv[e];
                bv[e] = c ? bv[e+st] : bv[e];
                bi[e] = c ? bi[e+st] : bi[e];
            }
        }
        u32 ti = (u32)(gbase + bi[0]);
        u32 vb = __float_as_uint(bv[0]);
        u32 r1 = __reduce_max_sync(0xffffffffu, vb);
        if (vb == r1) wred[p][wid] = ((u64)r1 << 32) | (u64)ti;
        if (tid == 0 && jp >= 0) sdeath[jp] = 0.0f;   // persist removal

        __syncthreads();

        u64 a0 = umax64(wred[p][0], wred[p][1]);
        u64 a1 = umax64(wred[p][2], wred[p][3]);
        a0 = umax64(a0, a1);

        if (tid == 0) {
            out[dgm_base + 2 * k + 0] = 0.0f;
            out[dgm_base + 2 * k + 1] = __uint_as_float((u32)(a0 >> 32));
        }
        jp = (int)(u32)a0;
        p ^= 1;
    }
}

extern "C" void kernel_launch(void* const* d_in, const int* in_sizes, int n_in,
                              void* d_out, int out_size)
{
    const float* x    = (const float*)d_in[0];
    const float* filt = (const float*)d_in[1];
    float* out        = (float*)d_out;

    int B = in_sizes[0] / (NPTS * 3);
    int F = in_sizes[1];

    ph_kernel<<<B, NT>>>(x, filt, out, B, F);
}

// round 17
// speedup vs baseline: 1.0980x; 1.0980x over previous
#include <cuda_runtime.h>
#include <math.h>

#define NPTS   2048
#define NT     128
#define NW     (NT/32)      // 4 warps
#define MAXPTS 100
#define F_INF  (__int_as_float(0x7f800000))

typedef unsigned long long u64;
typedef unsigned int       u32;

static __device__ __forceinline__ u64 umin64(u64 a, u64 b) { return a < b ? a : b; }
static __device__ __forceinline__ u64 umax64(u64 a, u64 b) { return a > b ? a : b; }

#define FMA2(d, a, b, c) \
    asm("fma.rn.f32x2 %0, %1, %2, %3;" : "=l"(d) : "l"(a), "l"(b), "l"(c))

static __device__ __forceinline__ u64 packf2(float lo, float hi) {
    return ((u64)__float_as_uint(hi) << 32) | (u64)__float_as_uint(lo);
}
static __device__ __forceinline__ float lof2(u64 v) { return __uint_as_float((u32)v); }
static __device__ __forceinline__ float hif2(u64 v) { return __uint_as_float((u32)(v >> 32)); }

// packed multi-warp state: raw coords in f32x2 pairs, sq/mk' scalar
template<int E> struct PRegs { u64 xp[E/2], yp[E/2], zp[E/2]; float sq[E], mk[E]; };
// unpacked state for the single-warp tail (R14-proven form)
template<int E> struct Regs { float x2[E], y2[E], z2[E], sq[E], mk[E]; };

// per-thread argmin: fold tail onto largest pow2 <= E, then halve (compare-select)
template<int E>
static __device__ __forceinline__ void argmin_tree(const float (&v)[E],
                                                   float& outv, int& outi)
{
    float bv[E]; int bi[E];
    #pragma unroll
    for (int e = 0; e < E; e++) { bv[e] = v[e]; bi[e] = e; }
    constexpr int T = ((E & (E - 1)) == 0) ? E : (E > 8 ? 8 : (E > 4 ? 4 : 2));
    #pragma unroll
    for (int e = T; e < E; e++) {
        bool c = bv[e] < bv[e - T];
        bv[e - T] = c ? bv[e] : bv[e - T];
        bi[e - T] = c ? bi[e] : bi[e - T];
    }
    #pragma unroll
    for (int st = T / 2; st >= 1; st >>= 1) {
        #pragma unroll
        for (int e = 0; e < st; e++) {
            bool c = bv[e + st] < bv[e];
            bv[e] = c ? bv[e + st] : bv[e];
            bi[e] = c ? bi[e + st] : bi[e];
        }
    }
    outv = bv[0]; outi = bi[0];
}

// ---------- packed multi-warp Prim phase ----------
// tbl = raw (x,y,z,|x|^2). mk' = min_j (sq_j - 2 x_j.x_e); tree on t = mk' + sq_e.
// Removal poison: sq_e = inf once (t stays inf forever). No per-step mk select.
template<int E>
static __device__ __forceinline__ void prim_runP(
    const float4* __restrict__ tbl, float* __restrict__ sdeath,
    u64 (&wred)[2][NW], PRegs<E>& R,
    int gbase, int tid, int wid,
    int& j, int& p, int step0, int nsteps)
{
    const float inf = F_INF;
    #pragma unroll 1
    for (int s = 0; s < nsteps; s++) {
        float4 q = tbl[j];                        // LDS.128 broadcast
        float m2x = -2.0f * q.x, m2y = -2.0f * q.y, m2z = -2.0f * q.z;
        u64 qx2 = packf2(m2x, m2x);
        u64 qy2 = packf2(m2y, m2y);
        u64 qz2 = packf2(m2z, m2z);
        u64 qw2 = packf2(q.w, q.w);

        #pragma unroll
        for (int e = 0; e < E; e++)               // one-time poison of removed vertex
            R.sq[e] = (gbase + e == j) ? inf : R.sq[e];

        float t[E];
        #pragma unroll
        for (int h = 0; h < E / 2; h++) {
            u64 acc;
            FMA2(acc, R.zp[h], qz2, qw2);
            FMA2(acc, R.yp[h], qy2, acc);
            FMA2(acc, R.xp[h], qx2, acc);         // acc = q.w - 2 x_j . x_e (pair)
            float a0 = lof2(acc), a1 = hif2(acc);
            float m0 = fminf(R.mk[2*h],   a0);
            float m1 = fminf(R.mk[2*h+1], a1);
            R.mk[2*h] = m0; R.mk[2*h+1] = m1;
            t[2*h]   = m0 + R.sq[2*h];            // true d^2 (inf if removed)
            t[2*h+1] = m1 + R.sq[2*h+1];
        }
        float tm; int te;
        argmin_tree<E>(t, tm, te);
        tm = fmaxf(tm, 0.0f);                     // >=0 -> u32 bit-order exact
        u32 ti = (u32)(gbase + te);

        u32 vb = __float_as_uint(tm);
        u32 r1 = __reduce_min_sync(0xffffffffu, vb);
        if (vb == r1) wred[p][wid] = ((u64)r1 << 32) | (u64)ti;

        __syncthreads();

        u64 a0 = umin64(wred[p][0], wred[p][1]);
        u64 a1 = umin64(wred[p][2], wred[p][3]);
        a0 = umin64(a0, a1);
        if (tid == 0) sdeath[step0 + s] = __uint_as_float((u32)(a0 >> 32));
        j = (int)(u32)a0;
        p ^= 1;
    }
}

// ---------- single-warp Prim phase (warp 0, no block barriers; R14 form) ----------
template<int E>
static __device__ __forceinline__ void prim_warp(
    const float4* __restrict__ tbl, float* __restrict__ sdeath,
    Regs<E>& R, int gbase, int lane, int& j, int step0, int nsteps)
{
    const float inf = F_INF;
    #pragma unroll 1
    for (int s = 0; s < nsteps; s++) {
        float4 q = tbl[j];
        #pragma unroll
        for (int e = 0; e < E; e++) {
            int gi = gbase + e;
            bool rem = (gi == j);
            float rs = rem ? inf : R.sq[e];
            R.sq[e] = rs;
            float acc = fmaf(q.x, R.x2[e], rs + q.w);
            acc = fmaf(q.y, R.y2[e], acc);
            acc = fmaf(q.z, R.z2[e], acc);
            float mi = rem ? inf : R.mk[e];
            R.mk[e] = fminf(mi, fabsf(acc));
        }
        float tm; int te;
        argmin_tree<E>(R.mk, tm, te);
        u32 ti = (u32)(gbase + te);

        u32 vb = __float_as_uint(tm);
        u32 r1 = __reduce_min_sync(0xffffffffu, vb);
        u32 msk = __ballot_sync(0xffffffffu, vb == r1);
        int src = __ffs(msk) - 1;
        j = __shfl_sync(0xffffffffu, (int)ti, src);
        if (lane == 0) sdeath[step0 + s] = __uint_as_float(r1);
    }
}

// ---------- packed block-wide compaction ----------
template<int E>
static __device__ __forceinline__ void compact_blockP(
    float4* tbl, float* smk, int* scnt,
    PRegs<E>& R, int gbase, int tid, int j, int newcap)
{
    const float inf = F_INF;
    #pragma unroll
    for (int e = 0; e < E; e++)
        if (gbase + e == j) R.sq[e] = inf;       // pending poison
    float4 win = tbl[j];                          // read winner BEFORE overwrite
    __syncthreads();
    if (tid == 0) { tbl[newcap - 1] = win; smk[newcap - 1] = inf; }
    int na = 0;
    #pragma unroll
    for (int e = 0; e < E; e++) na += (R.sq[e] != inf);
    int base = atomicAdd(scnt, na);
    #pragma unroll
    for (int h = 0; h < E / 2; h++) {
        float xs0 = lof2(R.xp[h]), xs1 = hif2(R.xp[h]);
        float ys0 = lof2(R.yp[h]), ys1 = hif2(R.yp[h]);
        float zs0 = lof2(R.zp[h]), zs1 = hif2(R.zp[h]);
        if (R.sq[2*h] != inf) {
            tbl[base] = make_float4(xs0, ys0, zs0, R.sq[2*h]);
            smk[base] = fmaxf(R.mk[2*h] + R.sq[2*h], 0.0f);
            base++;
        }
        if (R.sq[2*h+1] != inf) {
            tbl[base] = make_float4(xs1, ys1, zs1, R.sq[2*h+1]);
            smk[base] = fmaxf(R.mk[2*h+1] + R.sq[2*h+1], 0.0f);
            base++;
        }
    }
    __syncthreads();
}

template<int E>
static __device__ __forceinline__ void reloadP(
    const float4* tbl, const float* smk, PRegs<E>& R, int gbase, int cap)
{
    #pragma unroll
    for (int h = 0; h < E / 2; h++) {
        int i0 = gbase + 2*h, i1 = i0 + 1;
        float4 t0 = tbl[i0], t1 = tbl[i1];
        R.xp[h] = packf2(t0.x, t1.x);
        R.yp[h] = packf2(t0.y, t1.y);
        R.zp[h] = packf2(t0.z, t1.z);
        bool p0 = (i0 == cap - 1), p1 = (i1 == cap - 1);
        R.sq[2*h]   = p0 ? F_INF : t0.w;
        R.sq[2*h+1] = p1 ? F_INF : t1.w;
        R.mk[2*h]   = p0 ? F_INF : (smk[i0] - t0.w);   // deferred representation
        R.mk[2*h+1] = p1 ? F_INF : (smk[i1] - t1.w);
    }
}

// unpacked reload for the single-warp tail (raw tbl -> -2x regs, true mk)
template<int E>
static __device__ __forceinline__ void reload(
    const float4* tbl, const float* smk, Regs<E>& R, int gbase, int cap)
{
    #pragma unroll
    for (int e = 0; e < E; e++) {
        int i = gbase + e;
        float4 t = tbl[i];
        R.x2[e] = -2.0f * t.x; R.y2[e] = -2.0f * t.y; R.z2[e] = -2.0f * t.z;
        R.sq[e] = (i == cap - 1) ? F_INF : t.w;
        R.mk[e] = smk[i];
    }
}

__global__ __launch_bounds__(NT, 1)
void ph_kernel(const float* __restrict__ x,
               const float* __restrict__ filt,
               float* __restrict__ out,
               int B, int F)
{
    __shared__ __align__(16) float4 tbl[NPTS];     // raw (x,y,z,|x|^2), reused
    __shared__ __align__(16) float  sdeath[NPTS];
    __shared__ float  smk[1792];
    __shared__ __align__(16) u64 wred[2][NW];
    __shared__ int    scnt[8];

    const int b     = blockIdx.x;
    const int tid   = threadIdx.x;
    const int lane  = tid & 31;
    const int wid   = tid >> 5;
    const float inf = F_INF;

    const float* xb = x + (long)b * NPTS * 3;

    // ---- load: packed pairs (E=16), raw table ----
    PRegs<16> R1;
    {
        int gbase = tid << 4;
        #pragma unroll
        for (int h = 0; h < 8; h++) {
            int i0 = gbase + 2*h, i1 = i0 + 1;
            float a0 = xb[3*i0+0], c0 = xb[3*i0+1], d0 = xb[3*i0+2];
            float a1 = xb[3*i1+0], c1 = xb[3*i1+1], d1 = xb[3*i1+2];
            float s0 = fmaf(a0, a0, fmaf(c0, c0, d0 * d0));
            float s1 = fmaf(a1, a1, fmaf(c1, c1, d1 * d1));
            R1.xp[h] = packf2(a0, a1);
            R1.yp[h] = packf2(c0, c1);
            R1.zp[h] = packf2(d0, d1);
            R1.sq[2*h] = s0;  R1.sq[2*h+1] = s1;
            R1.mk[2*h] = inf; R1.mk[2*h+1] = inf;
            tbl[i0] = make_float4(a0, c0, d0, s0);
            tbl[i1] = make_float4(a1, c1, d1, s1);
        }
    }
    if (tid < 8) scnt[tid] = 0;
    __syncthreads();

    int j = 0, p = 0;

    // ---- staircase: compact every 256 steps (multi-warp region) ----
    prim_runP<16>(tbl, sdeath, wred, R1, tid << 4, tid, wid, j, p, 0, 256);

    compact_blockP<16>(tbl, smk, &scnt[0], R1, tid << 4, tid, j, 1792);
    PRegs<14> R2;
    reloadP<14>(tbl, smk, R2, tid * 14, 1792);
    j = 1791;
    prim_runP<14>(tbl, sdeath, wred, R2, tid * 14, tid, wid, j, p, 256, 256);

    compact_blockP<14>(tbl, smk, &scnt[1], R2, tid * 14, tid, j, 1536);
    PRegs<12> R3;
    reloadP<12>(tbl, smk, R3, tid * 12, 1536);
    j = 1535;
    prim_runP<12>(tbl, sdeath, wred, R3, tid * 12, tid, wid, j, p, 512, 256);

    compact_blockP<12>(tbl, smk, &scnt[2], R3, tid * 12, tid, j, 1280);
    PRegs<10> R4;
    reloadP<10>(tbl, smk, R4, tid * 10, 1280);
    j = 1279;
    prim_runP<10>(tbl, sdeath, wred, R4, tid * 10, tid, wid, j, p, 768, 256);

    compact_blockP<10>(tbl, smk, &scnt[3], R4, tid * 10, tid, j, 1024);
    PRegs<8> R5;
    reloadP<8>(tbl, smk, R5, tid << 3, 1024);
    j = 1023;
    prim_runP<8>(tbl, sdeath, wred, R5, tid << 3, tid, wid, j, p, 1024, 256);

    compact_blockP<8>(tbl, smk, &scnt[4], R5, tid << 3, tid, j, 768);
    PRegs<6> R6;
    reloadP<6>(tbl, smk, R6, tid * 6, 768);
    j = 767;
    prim_runP<6>(tbl, sdeath, wred, R6, tid * 6, tid, wid, j, p, 1280, 256);

    compact_blockP<6>(tbl, smk, &scnt[5], R6, tid * 6, tid, j, 512);
    PRegs<4> R7;
    reloadP<4>(tbl, smk, R7, tid << 2, 512);
    j = 511;
    prim_runP<4>(tbl, sdeath, wred, R7, tid << 2, tid, wid, j, p, 1536, 256);

    // -> 256: single warp, E8/lane, steps 1792..2046
    compact_blockP<4>(tbl, smk, &scnt[6], R7, tid << 2, tid, j, 256);
    if (wid == 0) {
        Regs<8> Q;
        reload<8>(tbl, smk, Q, lane << 3, 256);
        int jw = 255;
        prim_warp<8>(tbl, sdeath, Q, lane << 3, lane, jw, 1792, 255);
    }
    __syncthreads();

    // ---- d^2 -> death = sqrt(d2); pad slot 2047 with +INF ----
    #pragma unroll
    for (int e = 0; e < 16; e++) {
        int i = (tid << 4) + e;
        float d2 = sdeath[i];
        sdeath[i] = (i < NPTS - 1) ? sqrtf(d2) : inf;
    }
    __syncthreads();

    const long dgm_base = (long)b * 3 * MAXPTS * 2;                     // diagrams [B,3,100,2]
    const long bet_base = (long)B * 3 * MAXPTS * 2 + (long)b * 3 * F;   // betti    [B,3,F]

    // ---- zero-fill H1/H2 diagram slices and betti rows 1,2 ----
    for (int i = tid; i < 2 * MAXPTS * 2; i += NT)
        out[dgm_base + MAXPTS * 2 + i] = 0.0f;
    for (int i = tid; i < 2 * F; i += NT)
        out[bet_base + F + i] = 0.0f;

    // ---- Betti-0: one threshold per thread, float4 smem scan ----
    if (tid < F) {
        float ff = filt[tid];
        int cnt = 0;
        for (int i = 0; i < NPTS; i += 4) {
            float4 v = *reinterpret_cast<const float4*>(&sdeath[i]);
            cnt += (v.x <= ff) + (v.y <= ff) + (v.z <= ff) + (v.w <= ff);
        }
        out[bet_base + tid] = (float)(NPTS - cnt);
    }
    __syncthreads();

    // ---- top-100 deaths desc: iterative max extraction (R14 form) ----
    int jp = -1;
    p = 0;
    const int gbase = tid << 4;
    #pragma unroll 1
    for (int k = 0; k < MAXPTS; k++) {
        float bv[16]; int bi[16];
        #pragma unroll
        for (int e = 0; e < 16; e++) {
            int gi = gbase + e;
            float v = sdeath[gi];
            bv[e] = (gi == jp || gi == NPTS - 1) ? 0.0f : v;  // mask pending + INF pad
            bi[e] = e;
        }
        #pragma unroll
        for (int st = 8; st >= 1; st >>= 1) {
            #pragma unroll
            for (int e = 0; e < st; e++) {
                bool c = bv[e+st] > bv[e];
                bv[e] = c ? bv[e+st] : bv[e];
                bi[e] = c ? bi[e+st] : bi[e];
            }
        }
        u32 ti = (u32)(gbase + bi[0]);
        u32 vb = __float_as_uint(bv[0]);
        u32 r1 = __reduce_max_sync(0xffffffffu, vb);
        if (vb == r1) wred[p][wid] = ((u64)r1 << 32) | (u64)ti;
        if (tid == 0 && jp >= 0) sdeath[jp] = 0.0f;   // persist removal

        __syncthreads();

        u64 a0 = umax64(wred[p][0], wred[p][1]);
        u64 a1 = umax64(wred[p][2], wred[p][3]);
        a0 = umax64(a0, a1);

        if (tid == 0) {
            out[dgm_base + 2 * k + 0] = 0.0f;
            out[dgm_base + 2 * k + 1] = __uint_as_float((u32)(a0 >> 32));
        }
        jp = (int)(u32)a0;
        p ^= 1;
    }
}

extern "C" void kernel_launch(void* const* d_in, const int* in_sizes, int n_in,
                              void* d_out, int out_size)
{
    const float* x    = (const float*)d_in[0];
    const float* filt = (const float*)d_in[1];
    float* out        = (float*)d_out;

    int B = in_sizes[0] / (NPTS * 3);
    int F = in_sizes[1];

    ph_kernel<<<B, NT>>>(x, filt, out, B, F);
}